// round 1
// baseline (speedup 1.0000x reference)
#include <cuda_runtime.h>
#include <math.h>
#include <stdint.h>

#define BB    8
#define NN    2048
#define DIMC  1024
#define KDIM  2048           // 2*DIMC
#define DR    256
#define NE    4
#define DH    32
#define MTOK  16384          // B*N

// ---------------- device scratch (no allocations allowed) ----------------
__device__ float g_Wp[KDIM * DR];      // g-scaled reduce weight
__device__ float g_c[DR];              // colsum(g*W)
__device__ float g_dv[DR];             // b @ W
__device__ float g_w2bar[NE * 2 * DH]; // mean of w2 over each 128-col half
__device__ float g_b2bar[NE * 2];
__device__ float g_mean[MTOK];
__device__ float g_rstd[MTOK];
__device__ float g_z[(size_t)MTOK * DR];   // pre-LN2 reduced features
__device__ float g_px[MTOK];
__device__ float g_pt[MTOK];
__device__ float g_dd[2][BB * DIMC];       // |diff| sums
__device__ float g_sv[BB][2];              // score-net outputs
__device__ float g_imp[NE];
__device__ float g_load[NE];
__device__ float g_ox[(size_t)MTOK * DIMC]; // fallback scratch if d_out lacks space
__device__ float g_ot[(size_t)MTOK * DIMC];

// ---------------- prep0: zeros + w2bar/b2bar ----------------
__global__ void prep0_kernel(const float* __restrict__ w2, const float* __restrict__ b2) {
    int tid = threadIdx.x;
    if (tid < DR) { g_c[tid] = 0.f; g_dv[tid] = 0.f; }
    if (tid < NE) { g_imp[tid] = 0.f; g_load[tid] = 0.f; }
    for (int i = tid; i < 2 * BB * DIMC; i += 256) ((float*)g_dd)[i] = 0.f;
    {   // 256 threads = 4 experts * 2 halves * 32 hidden
        int e = tid >> 6, p = (tid >> 5) & 1, h = tid & 31;
        const float* base = w2 + ((size_t)e * DH + h) * DR + p * 128;
        float s = 0.f;
        for (int o = 0; o < 128; ++o) s += base[o];
        g_w2bar[(e * 2 + p) * DH + h] = s * (1.f / 128.f);
    }
    if (tid < NE * 2) {
        int e = tid >> 1, p = tid & 1;
        const float* base = b2 + (size_t)e * DR + p * 128;
        float s = 0.f;
        for (int o = 0; o < 128; ++o) s += base[o];
        g_b2bar[tid] = s * (1.f / 128.f);
    }
}

// ---------------- prep1: fold LN1 affine into GEMM weight ----------------
__global__ void prep1_kernel(const float* __restrict__ w_red,
                             const float* __restrict__ g1,
                             const float* __restrict__ b1) {
    int j = threadIdx.x;            // output col
    int i0 = blockIdx.x * 32;       // 64 blocks cover K=2048
    float ac = 0.f, ad = 0.f;
    for (int ii = 0; ii < 32; ++ii) {
        int i = i0 + ii;
        float w = w_red[(size_t)i * DR + j];
        float wp = g1[i] * w;
        g_Wp[(size_t)i * DR + j] = wp;
        ac += wp;
        ad += b1[i] * w;
    }
    atomicAdd(&g_c[j], ac);
    atomicAdd(&g_dv[j], ad);
}

// ---------------- row stats over concat(x,t) ----------------
__global__ void rowstats_kernel(const float* __restrict__ x, const float* __restrict__ t) {
    int w = threadIdx.x >> 5, lane = threadIdx.x & 31;
    int m = blockIdx.x * 8 + w;
    const float4* xr = (const float4*)(x + (size_t)m * DIMC);
    const float4* tr = (const float4*)(t + (size_t)m * DIMC);
    float s = 0.f, sq = 0.f;
    #pragma unroll
    for (int q = 0; q < 8; ++q) {
        float4 v = xr[lane + 32 * q];
        s += v.x + v.y + v.z + v.w;
        sq += v.x * v.x + v.y * v.y + v.z * v.z + v.w * v.w;
    }
    #pragma unroll
    for (int q = 0; q < 8; ++q) {
        float4 v = tr[lane + 32 * q];
        s += v.x + v.y + v.z + v.w;
        sq += v.x * v.x + v.y * v.y + v.z * v.z + v.w * v.w;
    }
    #pragma unroll
    for (int o = 16; o; o >>= 1) {
        s  += __shfl_xor_sync(0xffffffffu, s, o);
        sq += __shfl_xor_sync(0xffffffffu, sq, o);
    }
    if (lane == 0) {
        float mu = s * (1.f / 2048.f);
        float var = sq * (1.f / 2048.f) - mu * mu;
        g_mean[m] = mu;
        g_rstd[m] = rsqrtf(var + 1e-5f);
    }
}

// ---------------- fused LN1-GEMM: z = rstd*(A@Wp - mean*c) + d ----------------
#define GFETCH(kt) { \
    const float* asrc = ((kt) < 64) ? x : t; \
    const float* ap = asrc + (size_t)(m0 + arow) * DIMC + (((kt) * 16) & 1023) + acol; \
    pa0 = *(const float4*)ap; pa1 = *(const float4*)(ap + 4); \
    const float* bp = g_Wp + (size_t)((kt) * 16 + brow) * DR + j0 + bcol; \
    pb0 = *(const float4*)bp; pb1 = *(const float4*)(bp + 4); }

#define GSTORE(bufi) { \
    As[bufi][acol + 0][arow] = pa0.x; As[bufi][acol + 1][arow] = pa0.y; \
    As[bufi][acol + 2][arow] = pa0.z; As[bufi][acol + 3][arow] = pa0.w; \
    As[bufi][acol + 4][arow] = pa1.x; As[bufi][acol + 5][arow] = pa1.y; \
    As[bufi][acol + 6][arow] = pa1.z; As[bufi][acol + 7][arow] = pa1.w; \
    *(float4*)&Bs[bufi][brow][bcol] = pb0; *(float4*)&Bs[bufi][brow][bcol + 4] = pb1; }

__global__ __launch_bounds__(256, 2) void gemm_ln_kernel(const float* __restrict__ x,
                                                         const float* __restrict__ t) {
    __shared__ float As[2][16][136];  // padded for float4-aligned rows
    __shared__ float Bs[2][16][128];
    int tid = threadIdx.x;
    int j0 = blockIdx.x * 128;
    int m0 = blockIdx.y * 128;
    int arow = tid >> 1,  acol = (tid & 1) * 8;
    int brow = tid >> 4,  bcol = (tid & 15) * 8;
    int tr4 = (tid >> 4) * 4, tc4 = (tid & 15) * 4;

    float acc[8][8];
    #pragma unroll
    for (int i = 0; i < 8; ++i)
        #pragma unroll
        for (int j = 0; j < 8; ++j) acc[i][j] = 0.f;

    float4 pa0, pa1, pb0, pb1;
    GFETCH(0);
    GSTORE(0);
    __syncthreads();

    for (int kt = 0; kt < 128; ++kt) {
        int buf = kt & 1;
        if (kt < 127) GFETCH(kt + 1);
        #pragma unroll
        for (int kk = 0; kk < 16; ++kk) {
            float4 a0 = *(const float4*)&As[buf][kk][tr4];
            float4 a1 = *(const float4*)&As[buf][kk][64 + tr4];
            float4 b0 = *(const float4*)&Bs[buf][kk][tc4];
            float4 b1 = *(const float4*)&Bs[buf][kk][64 + tc4];
            float av[8] = {a0.x, a0.y, a0.z, a0.w, a1.x, a1.y, a1.z, a1.w};
            float bv[8] = {b0.x, b0.y, b0.z, b0.w, b1.x, b1.y, b1.z, b1.w};
            #pragma unroll
            for (int i = 0; i < 8; ++i)
                #pragma unroll
                for (int j = 0; j < 8; ++j)
                    acc[i][j] += av[i] * bv[j];
        }
        if (kt < 127) {
            __syncthreads();
            GSTORE(buf ^ 1);
            __syncthreads();
        }
    }

    // epilogue: LN1 correction terms
    float mu[8], rs[8], cj[8], dj[8];
    #pragma unroll
    for (int i = 0; i < 8; ++i) {
        int ri = m0 + ((i < 4) ? tr4 + i : 64 + tr4 + i - 4);
        mu[i] = g_mean[ri];
        rs[i] = g_rstd[ri];
    }
    #pragma unroll
    for (int j = 0; j < 8; ++j) {
        int cjj = j0 + ((j < 4) ? tc4 + j : 64 + tc4 + j - 4);
        cj[j] = g_c[cjj];
        dj[j] = g_dv[cjj];
    }
    #pragma unroll
    for (int i = 0; i < 8; ++i) {
        int ri = m0 + ((i < 4) ? tr4 + i : 64 + tr4 + i - 4);
        float* zp = g_z + (size_t)ri * DR + j0;
        float4 v;
        v.x = rs[i] * (acc[i][0] - mu[i] * cj[0]) + dj[0];
        v.y = rs[i] * (acc[i][1] - mu[i] * cj[1]) + dj[1];
        v.z = rs[i] * (acc[i][2] - mu[i] * cj[2]) + dj[2];
        v.w = rs[i] * (acc[i][3] - mu[i] * cj[3]) + dj[3];
        *(float4*)(zp + tc4) = v;
        v.x = rs[i] * (acc[i][4] - mu[i] * cj[4]) + dj[4];
        v.y = rs[i] * (acc[i][5] - mu[i] * cj[5]) + dj[5];
        v.z = rs[i] * (acc[i][6] - mu[i] * cj[6]) + dj[6];
        v.w = rs[i] * (acc[i][7] - mu[i] * cj[7]) + dj[7];
        *(float4*)(zp + 64 + tc4) = v;
    }
}

// ---------------- MoE: LN2 + gating + expert layer-1 + pooled prompt ----------------
// dynamic smem layout (floats):
//   yf[128*257] | w1s[8192] | wgs[1024] | g2s[256] | b2s[256] | gates[512] | sImp[4] | sLoad[4]
#define MOE_SMEM_FLOATS (128 * 257 + 8192 + 1024 + 256 + 256 + 512 + 4 + 4)

__global__ __launch_bounds__(256, 1) void moe_kernel(const float* __restrict__ wgate,
                                                     const int* __restrict__ taskp,
                                                     const float* __restrict__ g2,
                                                     const float* __restrict__ b2g,
                                                     const float* __restrict__ w1,
                                                     const float* __restrict__ b1e) {
    extern __shared__ float sm[];
    float* yf    = sm;
    float* w1s   = yf + 128 * 257;
    float* wgs   = w1s + 8192;
    float* g2s   = wgs + 1024;
    float* b2s   = g2s + 256;
    float* gates = b2s + 256;
    float* sImp  = gates + 512;
    float* sLoad = sImp + 4;

    int tid = threadIdx.x, lane = tid & 31, w = tid >> 5;
    int m0 = blockIdx.x * 128;
    int task = taskp[0];

    g2s[tid] = g2[tid];
    b2s[tid] = b2g[tid];
    ((float4*)wgs)[tid] = ((const float4*)(wgate + (size_t)task * DR * NE))[tid];
    if (tid < 8) { sImp[tid & 3] = 0.f; sLoad[tid & 3] = 0.f; }
    __syncthreads();

    // LN2 + logits + gating: one warp covers 16 rows
    for (int rr = 0; rr < 16; ++rr) {
        int r = w * 16 + rr;
        int m = m0 + r;
        const float* zr = g_z + (size_t)m * DR;
        float ev[8];
        float s = 0.f, sq = 0.f;
        #pragma unroll
        for (int i = 0; i < 8; ++i) {
            float v = zr[lane + 32 * i];
            ev[i] = v; s += v; sq += v * v;
        }
        #pragma unroll
        for (int o = 16; o; o >>= 1) {
            s  += __shfl_xor_sync(0xffffffffu, s, o);
            sq += __shfl_xor_sync(0xffffffffu, sq, o);
        }
        float muv = s * (1.f / 256.f);
        float rsv = rsqrtf(sq * (1.f / 256.f) - muv * muv + 1e-5f);
        float l0 = 0.f, l1 = 0.f, l2 = 0.f, l3 = 0.f;
        #pragma unroll
        for (int i = 0; i < 8; ++i) {
            int j = lane + 32 * i;
            float yv = (ev[i] - muv) * rsv * g2s[j] + b2s[j];
            yf[r * 257 + j] = yv;
            float4 wg = *(const float4*)&wgs[j * 4];
            l0 += yv * wg.x; l1 += yv * wg.y; l2 += yv * wg.z; l3 += yv * wg.w;
        }
        #pragma unroll
        for (int o = 16; o; o >>= 1) {
            l0 += __shfl_xor_sync(0xffffffffu, l0, o);
            l1 += __shfl_xor_sync(0xffffffffu, l1, o);
            l2 += __shfl_xor_sync(0xffffffffu, l2, o);
            l3 += __shfl_xor_sync(0xffffffffu, l3, o);
        }
        if (lane == 0) {
            float lv[4] = {l0, l1, l2, l3};
            int i0 = 0; float v0 = lv[0];
            #pragma unroll
            for (int e = 1; e < 4; ++e) if (lv[e] > v0) { v0 = lv[e]; i0 = e; }
            int i1 = -1; float v1 = -1e30f;
            #pragma unroll
            for (int e = 0; e < 4; ++e) if (e != i0 && lv[e] > v1) { v1 = lv[e]; i1 = e; }
            float ex = __expf(v1 - v0);
            float inv = 1.f / (1.f + ex);
            float ga = inv, gb = ex * inv;
            gates[r * 4 + 0] = 0.f; gates[r * 4 + 1] = 0.f;
            gates[r * 4 + 2] = 0.f; gates[r * 4 + 3] = 0.f;
            gates[r * 4 + i0] = ga;
            gates[r * 4 + i1] = gb;
            atomicAdd(&sImp[i0], ga);  atomicAdd(&sImp[i1], gb);
            atomicAdd(&sLoad[i0], 1.f); atomicAdd(&sLoad[i1], 1.f);
        }
    }
    __syncthreads();
    if (tid < 4) {
        atomicAdd(&g_imp[tid], sImp[tid]);
        atomicAdd(&g_load[tid], sLoad[tid]);
    }

    // expert first layer, dense over all 4 experts, gate-weighted pooled output
    int r2 = tid >> 1, hb = (tid & 1) * 16;
    float rowPX = 0.f, rowPT = 0.f;
    for (int e = 0; e < NE; ++e) {
        __syncthreads();
        const float* w1p = w1 + (size_t)e * (DR * DH);
        #pragma unroll
        for (int q = 0; q < 32; ++q) w1s[tid + 256 * q] = w1p[tid + 256 * q];
        __syncthreads();
        float facc[16];
        #pragma unroll
        for (int i = 0; i < 16; ++i) facc[i] = b1e[e * DH + hb + i];
        const float* yr = yf + r2 * 257;
        #pragma unroll 4
        for (int k = 0; k < 256; ++k) {
            float yv = yr[k];
            const float4* wk = (const float4*)&w1s[k * 32 + hb];
            float4 wa = wk[0], wb = wk[1], wc = wk[2], wd = wk[3];
            facc[0]  += yv * wa.x; facc[1]  += yv * wa.y; facc[2]  += yv * wa.z; facc[3]  += yv * wa.w;
            facc[4]  += yv * wb.x; facc[5]  += yv * wb.y; facc[6]  += yv * wb.z; facc[7]  += yv * wb.w;
            facc[8]  += yv * wc.x; facc[9]  += yv * wc.y; facc[10] += yv * wc.z; facc[11] += yv * wc.w;
            facc[12] += yv * wd.x; facc[13] += yv * wd.y; facc[14] += yv * wd.z; facc[15] += yv * wd.w;
        }
        float px = 0.f, pt = 0.f;
        #pragma unroll
        for (int i = 0; i < 16; ++i) {
            float h = fmaxf(facc[i], 0.f);
            px += h * g_w2bar[(e * 2 + 0) * DH + hb + i];
            pt += h * g_w2bar[(e * 2 + 1) * DH + hb + i];
        }
        px += __shfl_xor_sync(0xffffffffu, px, 1);
        pt += __shfl_xor_sync(0xffffffffu, pt, 1);
        float gv = gates[r2 * 4 + e];
        rowPX += gv * (px + g_b2bar[e * 2 + 0]);
        rowPT += gv * (pt + g_b2bar[e * 2 + 1]);
    }
    if ((tid & 1) == 0) {
        int m = m0 + r2;
        g_px[m] = 1.f / (1.f + expf(-rowPX));
        g_pt[m] = 1.f / (1.f + expf(-rowPT));
    }
}

// ---------------- aux loss (scalar) ----------------
__global__ void aux_kernel(float* auxp) {
    if (threadIdx.x == 0) {
        float mi = 0.f, ml = 0.f;
        #pragma unroll
        for (int e = 0; e < NE; ++e) { mi += g_imp[e]; ml += g_load[e]; }
        mi *= 0.25f; ml *= 0.25f;
        float vi = 0.f, vl = 0.f;
        #pragma unroll
        for (int e = 0; e < NE; ++e) {
            float a = g_imp[e] - mi; vi += a * a;
            float b = g_load[e] - ml; vl += b * b;
        }
        vi *= 0.25f; vl *= 0.25f;
        auxp[0] = vi / (mi * mi + 1e-10f) + vl / (ml * ml + 1e-10f);
    }
}

// ---------------- out_x/out_t + |diff| reduction over N ----------------
__global__ void outxt_kernel(const float* __restrict__ x, const float* __restrict__ t,
                             const float* __restrict__ past_x, const float* __restrict__ past_t,
                             const float* __restrict__ modal, const int* __restrict__ taskp,
                             float* __restrict__ ox, float* __restrict__ ot) {
    int tid = threadIdx.x;
    int nt = blockIdx.x;  // 16 n-tiles of 128
    int b = blockIdx.y;   // 8
    int ct = blockIdx.z;  // 4 c-tiles of 256
    int c = ct * 256 + tid;
    int task = taskp[0];
    float msx = modal[(size_t)(task * 2 + 0) * DIMC + c];
    float mst = modal[(size_t)(task * 2 + 1) * DIMC + c];
    float a1 = 0.f, a2 = 0.f;
    for (int nn = 0; nn < 128; ++nn) {
        size_t m = (size_t)b * NN + nt * 128 + nn;
        size_t idx = m * DIMC + c;
        float p1 = g_px[m], p2 = g_pt[m];
        float vx = p1 * x[idx] + msx;
        float vt = p2 * t[idx] + mst;
        ox[idx] = vx;
        ot[idx] = vt;
        a1 += fabsf(vx - past_x[idx]);
        a2 += fabsf(vt - past_t[idx]);
    }
    atomicAdd(&g_dd[0][b * DIMC + c], a1);
    atomicAdd(&g_dd[1][b * DIMC + c], a2);
}

// ---------------- score net: s = relu(d @ ws1) @ ws2 ----------------
__global__ void score_kernel(const float* __restrict__ ws1, const float* __restrict__ ws2) {
    __shared__ float d1s[1024], d2s[1024];
    __shared__ float r1s[256], r2s[256];
    int b = blockIdx.x, tid = threadIdx.x;
    #pragma unroll
    for (int q = 0; q < 4; ++q) {
        int i = tid + 256 * q;
        d1s[i] = g_dd[0][b * DIMC + i] * (1.f / 2048.f);
        d2s[i] = g_dd[1][b * DIMC + i] * (1.f / 2048.f);
    }
    __syncthreads();
    float acc1[4] = {0.f, 0.f, 0.f, 0.f};
    float acc2[4] = {0.f, 0.f, 0.f, 0.f};
    for (int i = 0; i < 1024; ++i) {
        float v1 = d1s[i], v2 = d2s[i];
        #pragma unroll
        for (int q = 0; q < 4; ++q) {
            float wv = ws1[(size_t)i * DIMC + tid + 256 * q];
            acc1[q] += v1 * wv;
            acc2[q] += v2 * wv;
        }
    }
    float s1 = 0.f, s2 = 0.f;
    #pragma unroll
    for (int q = 0; q < 4; ++q) {
        float w2v = ws2[tid + 256 * q];
        s1 += fmaxf(acc1[q], 0.f) * w2v;
        s2 += fmaxf(acc2[q], 0.f) * w2v;
    }
    r1s[tid] = s1; r2s[tid] = s2;
    __syncthreads();
    for (int o = 128; o; o >>= 1) {
        if (tid < o) { r1s[tid] += r1s[tid + o]; r2s[tid] += r2s[tid + o]; }
        __syncthreads();
    }
    if (tid == 0) { g_sv[b][0] = r1s[0]; g_sv[b][1] = r2s[0]; }
}

// ---------------- final combine: out = w1*out_x + w0*out_t ----------------
__global__ void combine_kernel(const float* __restrict__ ox, const float* __restrict__ ot,
                               float* __restrict__ out) {
    size_t base = (size_t)blockIdx.x * 2048 + threadIdx.x;
    int b = blockIdx.x >> 10;   // 1024 blocks per batch (2048*1024 elems / 2048 per block)
    float s1 = g_sv[b][0], s2 = g_sv[b][1];
    float mx = fmaxf(s1, s2);
    float e1 = expf(s1 - mx), e2 = expf(s2 - mx);
    float inv = 1.f / (e1 + e2);
    float w0 = e1 * inv, w1 = e2 * inv;   // w0 <- s1, w1 <- s2
    #pragma unroll
    for (int q = 0; q < 8; ++q) {
        size_t i = base + 256 * q;
        out[i] = w1 * ox[i] + w0 * ot[i];
    }
}

// ---------------- launch ----------------
extern "C" void kernel_launch(void* const* d_in, const int* in_sizes, int n_in,
                              void* d_out, int out_size) {
    const float* x      = (const float*)d_in[0];
    const float* t      = (const float*)d_in[1];
    const float* past_x = (const float*)d_in[2];
    const float* past_t = (const float*)d_in[3];
    const int*   taskp  = (const int*)  d_in[4];
    const float* ln1_g  = (const float*)d_in[5];
    const float* ln1_b  = (const float*)d_in[6];
    const float* w_red  = (const float*)d_in[7];
    const float* ln2_g  = (const float*)d_in[8];
    const float* ln2_b  = (const float*)d_in[9];
    const float* w_gate = (const float*)d_in[10];
    const float* w1     = (const float*)d_in[11];
    const float* b1e    = (const float*)d_in[12];
    const float* w2     = (const float*)d_in[13];
    const float* b2     = (const float*)d_in[14];
    const float* modal  = (const float*)d_in[15];
    const float* ws1    = (const float*)d_in[16];
    const float* ws2    = (const float*)d_in[17];

    float* out = (float*)d_out;
    const size_t OUTN = (size_t)MTOK * DIMC;
    bool full = ((size_t)(unsigned)out_size >= 3 * OUTN + 1);

    float *ox, *ot;
    if (full) {
        ox = out + OUTN + 1;     // layout: out | aux | out_x | out_t
        ot = ox + OUTN;
    } else {
        void* p;
        cudaGetSymbolAddress(&p, g_ox); ox = (float*)p;
        cudaGetSymbolAddress(&p, g_ot); ot = (float*)p;
    }

    prep0_kernel<<<1, 256>>>(w2, b2);
    prep1_kernel<<<64, 256>>>(w_red, ln1_g, ln1_b);
    rowstats_kernel<<<2048, 256>>>(x, t);
    gemm_ln_kernel<<<dim3(2, 128), 256>>>(x, t);

    const int moe_smem = MOE_SMEM_FLOATS * (int)sizeof(float);
    cudaFuncSetAttribute(moe_kernel, cudaFuncAttributeMaxDynamicSharedMemorySize, moe_smem);
    moe_kernel<<<128, 256, moe_smem>>>(w_gate, taskp, ln2_g, ln2_b, w1, b1e);

    if (full) aux_kernel<<<1, 32>>>(out + OUTN);
    outxt_kernel<<<dim3(16, 8, 4), 256>>>(x, t, past_x, past_t, modal, taskp, ox, ot);
    score_kernel<<<8, 256>>>(ws1, ws2);
    combine_kernel<<<8192, 256>>>(ox, ot, out);
}